// round 1
// baseline (speedup 1.0000x reference)
#include <cuda_runtime.h>
#include <stdint.h>

// PenalizedMSELoss: mean(w * (x - t)^2), w = 3.0 if (4.5 < x < 5.5 && t != 5) else 1.0
// N = 33554432. Pure HBM-streaming reduction.

#define LABEL_V   5
#define PW        3.0f
#define LOWER_V   4.5f
#define UPPER_V   5.5f

#define NBLOCKS   1184          // 148 SMs * 8
#define NTHREADS  256
#define MAX_PARTIALS 4096

__device__ int   g_is64;
__device__ float g_partials[MAX_PARTIALS];

// --- kernel 1: detect target dtype (int64 vs int32 memory layout) ---------
// If target is int64 (values 0..9), every odd 32-bit word is 0.
// If int32, odd words are uniform 0..9 values -> some nonzero (256 samples).
__global__ void detect_kernel(const int* __restrict__ t_words) {
    if (blockIdx.x == 0 && threadIdx.x == 0) {
        int is64 = 1;
        #pragma unroll 8
        for (int i = 1; i < 512; i += 2) {
            if (t_words[i] != 0) { is64 = 0; break; }
        }
        g_is64 = is64;
    }
}

__device__ __forceinline__ float term(float x, int t) {
    float tf   = (float)t;
    float d    = x - tf;
    bool  pen  = (x > LOWER_V) & (x < UPPER_V) & (t != LABEL_V);
    float w    = pen ? PW : 1.0f;
    return w * d * d;
}

__device__ __forceinline__ float warp_sum(float v) {
    #pragma unroll
    for (int o = 16; o > 0; o >>= 1)
        v += __shfl_down_sync(0xffffffffu, v, o);
    return v;
}

// --- kernel 2: per-block partial sums ------------------------------------
__global__ __launch_bounds__(NTHREADS) void mse_partial_kernel(
    const float* __restrict__ x,
    const void*  __restrict__ tv,
    int n)
{
    const int tid    = blockIdx.x * blockDim.x + threadIdx.x;
    const int stride = gridDim.x * blockDim.x;
    const int n4     = n >> 2;
    const int is64   = g_is64;

    float acc = 0.0f;
    const float4* __restrict__ x4 = (const float4*)x;

    if (is64) {
        const longlong2* __restrict__ t2 = (const longlong2*)tv;
        for (int i = tid; i < n4; i += stride) {
            float4    xv = x4[i];
            longlong2 ta = t2[2 * i];
            longlong2 tb = t2[2 * i + 1];
            acc += term(xv.x, (int)ta.x);
            acc += term(xv.y, (int)ta.y);
            acc += term(xv.z, (int)tb.x);
            acc += term(xv.w, (int)tb.y);
        }
        // scalar tail (N % 4)
        const long long* __restrict__ ts = (const long long*)tv;
        for (int i = (n4 << 2) + tid; i < n; i += stride)
            acc += term(x[i], (int)ts[i]);
    } else {
        const int4* __restrict__ t4 = (const int4*)tv;
        for (int i = tid; i < n4; i += stride) {
            float4 xv = x4[i];
            int4   ti = t4[i];
            acc += term(xv.x, ti.x);
            acc += term(xv.y, ti.y);
            acc += term(xv.z, ti.z);
            acc += term(xv.w, ti.w);
        }
        const int* __restrict__ ts = (const int*)tv;
        for (int i = (n4 << 2) + tid; i < n; i += stride)
            acc += term(x[i], ts[i]);
    }

    // block reduction: warp shuffle + shared
    __shared__ float ssum[NTHREADS / 32];
    float w = warp_sum(acc);
    int lane = threadIdx.x & 31;
    int wid  = threadIdx.x >> 5;
    if (lane == 0) ssum[wid] = w;
    __syncthreads();
    if (wid == 0) {
        float v = (lane < NTHREADS / 32) ? ssum[lane] : 0.0f;
        v = warp_sum(v);
        if (lane == 0) g_partials[blockIdx.x] = v;
    }
}

// --- kernel 3: final deterministic reduce + mean -------------------------
__global__ __launch_bounds__(1024) void mse_final_kernel(float* __restrict__ out,
                                                         int nblocks, float inv_n)
{
    __shared__ float ssum[32];
    float acc = 0.0f;
    for (int i = threadIdx.x; i < nblocks; i += 1024)
        acc += g_partials[i];
    float w = warp_sum(acc);
    int lane = threadIdx.x & 31;
    int wid  = threadIdx.x >> 5;
    if (lane == 0) ssum[wid] = w;
    __syncthreads();
    if (wid == 0) {
        float v = (lane < 32) ? ssum[lane] : 0.0f;
        v = warp_sum(v);
        if (lane == 0) out[0] = v * inv_n;
    }
}

extern "C" void kernel_launch(void* const* d_in, const int* in_sizes, int n_in,
                              void* d_out, int out_size)
{
    const float* x  = (const float*)d_in[0];
    const void*  tv = d_in[1];
    float*       out = (float*)d_out;
    int n = in_sizes[0];

    detect_kernel<<<1, 32>>>((const int*)tv);
    mse_partial_kernel<<<NBLOCKS, NTHREADS>>>(x, tv, n);
    mse_final_kernel<<<1, 1024>>>(out, NBLOCKS, 1.0f / (float)n);
}

// round 2
// speedup vs baseline: 1.0457x; 1.0457x over previous
#include <cuda_runtime.h>
#include <stdint.h>

// PenalizedMSELoss: mean(w * (x - t)^2), w = 3.0 if (4.5 < x < 5.5 && t != 5) else 1.0
// N = 33554432. Pure HBM-streaming reduction. Single fused kernel:
//   per-block dtype detect + grid-stride partial sums + last-block final reduce.

#define LABEL_V   5
#define PW        3.0f
#define LOWER_V   4.5f
#define UPPER_V   5.5f

#define NBLOCKS   1184          // 148 SMs * 8 CTAs (256 thr -> 2048 thr/SM)
#define NTHREADS  256

__device__ float         g_partials[NBLOCKS];
__device__ unsigned int  g_counter = 0;

__device__ __forceinline__ float term(float x, int t) {
    float tf  = (float)t;
    float d   = x - tf;
    bool  pen = (x > LOWER_V) & (x < UPPER_V) & (t != LABEL_V);
    float w   = pen ? PW : 1.0f;
    return w * d * d;
}

__device__ __forceinline__ float warp_sum(float v) {
    #pragma unroll
    for (int o = 16; o > 0; o >>= 1)
        v += __shfl_down_sync(0xffffffffu, v, o);
    return v;
}

__device__ __forceinline__ float block_sum(float v, float* ssum) {
    float w = warp_sum(v);
    int lane = threadIdx.x & 31;
    int wid  = threadIdx.x >> 5;
    if (lane == 0) ssum[wid] = w;
    __syncthreads();
    float r = 0.0f;
    if (wid == 0) {
        float t = (lane < NTHREADS / 32) ? ssum[lane] : 0.0f;
        r = warp_sum(t);
    }
    return r;   // valid in warp 0 lane 0
}

__global__ __launch_bounds__(NTHREADS) void mse_fused_kernel(
    const float* __restrict__ x,
    const void*  __restrict__ tv,
    float* __restrict__ out,
    int n, float inv_n)
{
    __shared__ float ssum[NTHREADS / 32];
    __shared__ bool  s_last;

    // ---- dtype detect (per-block, L2-broadcast after first touch) --------
    // int64 targets (values 0..9) => every odd 32-bit word is zero.
    // int32 targets => odd words are uniform 0..9, some nonzero among 256.
    const int* tw = (const int*)tv;
    int any_odd_nonzero = __syncthreads_or(tw[2 * threadIdx.x + 1] != 0);
    const bool is64 = (any_odd_nonzero == 0);

    // ---- main grid-stride loop, unroll x2 (4 indep LDG.128 per iter) -----
    const int tid    = blockIdx.x * blockDim.x + threadIdx.x;
    const int stride = gridDim.x * blockDim.x;
    const int n4     = n >> 2;

    float acc = 0.0f;
    const float4* __restrict__ x4 = (const float4*)x;

    if (!is64) {
        const int4* __restrict__ t4 = (const int4*)tv;
        int i = tid;
        for (; i + stride < n4; i += 2 * stride) {
            float4 xa = __ldcs(&x4[i]);
            float4 xb = __ldcs(&x4[i + stride]);
            int4   ta = __ldcs(&t4[i]);
            int4   tb = __ldcs(&t4[i + stride]);
            acc += term(xa.x, ta.x); acc += term(xa.y, ta.y);
            acc += term(xa.z, ta.z); acc += term(xa.w, ta.w);
            acc += term(xb.x, tb.x); acc += term(xb.y, tb.y);
            acc += term(xb.z, tb.z); acc += term(xb.w, tb.w);
        }
        if (i < n4) {
            float4 xa = __ldcs(&x4[i]);
            int4   ta = __ldcs(&t4[i]);
            acc += term(xa.x, ta.x); acc += term(xa.y, ta.y);
            acc += term(xa.z, ta.z); acc += term(xa.w, ta.w);
        }
        const int* __restrict__ ts = (const int*)tv;
        for (int j = (n4 << 2) + tid; j < n; j += stride)
            acc += term(x[j], ts[j]);
    } else {
        const longlong2* __restrict__ t2 = (const longlong2*)tv;
        for (int i = tid; i < n4; i += stride) {
            float4    xv = __ldcs(&x4[i]);
            longlong2 ta = __ldcs(&t2[2 * i]);
            longlong2 tb = __ldcs(&t2[2 * i + 1]);
            acc += term(xv.x, (int)ta.x); acc += term(xv.y, (int)ta.y);
            acc += term(xv.z, (int)tb.x); acc += term(xv.w, (int)tb.y);
        }
        const long long* __restrict__ ts = (const long long*)tv;
        for (int j = (n4 << 2) + tid; j < n; j += stride)
            acc += term(x[j], (int)ts[j]);
    }

    // ---- block reduce -> partials ---------------------------------------
    float bs = block_sum(acc, ssum);
    if (threadIdx.x == 0) {
        g_partials[blockIdx.x] = bs;
        __threadfence();
        unsigned int done = atomicAdd(&g_counter, 1u);
        s_last = (done == gridDim.x - 1);
    }
    __syncthreads();

    // ---- last arriving block: deterministic final reduce -----------------
    if (s_last) {
        __threadfence();                 // acquire all partials
        float fa = 0.0f;
        // fixed order per thread: i, i+256, ... -> bitwise deterministic
        for (int i = threadIdx.x; i < NBLOCKS; i += NTHREADS)
            fa += g_partials[i];
        __syncthreads();                 // ssum reuse barrier
        float total = block_sum(fa, ssum);
        if (threadIdx.x == 0) {
            out[0] = total * inv_n;
            g_counter = 0;               // reset for next graph replay
        }
    }
}

extern "C" void kernel_launch(void* const* d_in, const int* in_sizes, int n_in,
                              void* d_out, int out_size)
{
    const float* x  = (const float*)d_in[0];
    const void*  tv = d_in[1];
    float*       out = (float*)d_out;
    int n = in_sizes[0];

    mse_fused_kernel<<<NBLOCKS, NTHREADS>>>(x, tv, out, n, 1.0f / (float)n);
}